// round 15
// baseline (speedup 1.0000x reference)
#include <cuda_runtime.h>
#include <cuda_bf16.h>
#include <cstdint>

// Shapes (fixed by the problem)
#define B_   32
#define H_   8
#define C_   64
#define L_   1024
#define HC_  512          // H_*C_
#define K_   6            // int(log(1024)) = 6
#define G_   32           // row-groups per batch in stage-1 reduction
#define RPG_ 16           // rows per group (HC_/G_)
#define TROWS 4           // k_agg rows per block (2 interleaved pairs)

// Scratch (no allocations allowed -> __device__ globals)
__device__ float g_partial[B_ * G_ * L_];   // 4 MB
__device__ float g_meanv[B_ * L_];          // 128 KB
__device__ int   g_idx[K_];
__device__ float g_wts[B_ * K_];

// ---------------------------------------------------------------------------
// packed f32x2 helpers (Blackwell FFMA2 — only reachable via PTX)
// ---------------------------------------------------------------------------
__device__ __forceinline__ uint64_t pack2(float x, float y) {
    uint64_t r; asm("mov.b64 %0, {%1, %2};" : "=l"(r) : "f"(x), "f"(y)); return r;
}
__device__ __forceinline__ void unpack2(uint64_t v, float& x, float& y) {
    asm("mov.b64 {%0, %1}, %2;" : "=f"(x), "=f"(y) : "l"(v));
}
__device__ __forceinline__ uint64_t fma2(uint64_t a, uint64_t b, uint64_t c) {
    uint64_t d;
    asm("fma.rn.f32x2 %0, %1, %2, %3;" : "=l"(d) : "l"(a), "l"(b), "l"(c));
    return d;
}

// ---------------------------------------------------------------------------
// Kernel 1: partial reduce of corr over 16-row groups (float4, __ldcs so corr
// streams through L2 evict-first), PLUS an L2 prefetch sweep of this block's
// 64KB slice of `values` — overlaps values' HBM reads with the reduction so
// k_agg later hits L2. grid (B_, G_) = 1024 blocks, 256 threads.
// ---------------------------------------------------------------------------
__global__ __launch_bounds__(256) void k_partial(const float* __restrict__ corr,
                                                 const float* __restrict__ values) {
    const int b = blockIdx.x;
    const int g = blockIdx.y;
    const int t = threadIdx.x;
    const float4* __restrict__ base =
        reinterpret_cast<const float4*>(corr) +
        ((size_t)b * HC_ + (size_t)g * RPG_) * (L_ / 4) + t;

    float4 a0 = make_float4(0.f, 0.f, 0.f, 0.f);
    float4 a1 = make_float4(0.f, 0.f, 0.f, 0.f);
#pragma unroll
    for (int r = 0; r < RPG_; r += 2) {
        float4 v0 = __ldcs(&base[(size_t)r * (L_ / 4)]);
        float4 v1 = __ldcs(&base[(size_t)(r + 1) * (L_ / 4)]);
        a0.x += v0.x; a0.y += v0.y; a0.z += v0.z; a0.w += v0.w;
        a1.x += v1.x; a1.y += v1.y; a1.z += v1.z; a1.w += v1.w;
    }
    float4 s;
    s.x = a0.x + a1.x; s.y = a0.y + a1.y; s.z = a0.z + a1.z; s.w = a0.w + a1.w;
    reinterpret_cast<float4*>(g_partial)[((size_t)(b * G_ + g)) * (L_ / 4) + t] = s;

    // prefetch this block's 64KB slice of values into L2 (512 x 128B lines)
    const char* vbase = reinterpret_cast<const char*>(values) +
                        ((size_t)(b * G_ + g)) * 65536;
#pragma unroll
    for (int q = 0; q < 2; ++q)
        asm volatile("prefetch.global.L2 [%0];" :: "l"(vbase + (size_t)(t + q * 256) * 128));
}

// ---------------------------------------------------------------------------
// Kernel 2: combine partials -> mean_value[b,l]. grid (B_,4), 256 threads.
// ---------------------------------------------------------------------------
__global__ __launch_bounds__(256) void k_combine() {
    const int b = blockIdx.x;
    const int l = blockIdx.y * 256 + threadIdx.x;
    float s = 0.f;
#pragma unroll
    for (int g = 0; g < G_; ++g)
        s += g_partial[((size_t)b * G_ + g) * L_ + l];
    g_meanv[(size_t)b * L_ + l] = s * (1.0f / (float)HC_);
}

// ---------------------------------------------------------------------------
// Kernel 3: single block, 256 threads. batch-mean, top-6 (argmax iterate with
// smaller-index tie-break -> same SET as lax.top_k; order irrelevant since the
// final softmax-weighted sum is permutation invariant), per-batch softmax.
// ---------------------------------------------------------------------------
__global__ __launch_bounds__(256) void k_topk_softmax() {
    __shared__ float sm[L_];
    __shared__ float wval[8];
    __shared__ int   widx[8];
    __shared__ int   s_idx[K_];

    const int t   = threadIdx.x;
    const int wid = t >> 5;
    const int lid = t & 31;

#pragma unroll
    for (int j = 0; j < 4; ++j) {
        const int l = t + j * 256;
        float s = 0.f;
#pragma unroll 8
        for (int b = 0; b < B_; ++b) s += g_meanv[(size_t)b * L_ + l];
        sm[l] = s;
    }
    __syncthreads();

    for (int k = 0; k < K_; ++k) {
        float bv = -3.0e38f; int bi = 0x7fffffff;
#pragma unroll
        for (int j = 0; j < 4; ++j) {
            const int l = t + j * 256;
            const float v = sm[l];
            if (v > bv || (v == bv && l < bi)) { bv = v; bi = l; }
        }
#pragma unroll
        for (int off = 16; off > 0; off >>= 1) {
            float v2 = __shfl_down_sync(0xffffffffu, bv, off);
            int   i2 = __shfl_down_sync(0xffffffffu, bi, off);
            if (v2 > bv || (v2 == bv && i2 < bi)) { bv = v2; bi = i2; }
        }
        if (lid == 0) { wval[wid] = bv; widx[wid] = bi; }
        __syncthreads();
        if (t == 0) {
            float fv = wval[0]; int fi = widx[0];
#pragma unroll
            for (int w = 1; w < 8; ++w) {
                if (wval[w] > fv || (wval[w] == fv && widx[w] < fi)) {
                    fv = wval[w]; fi = widx[w];
                }
            }
            s_idx[k] = fi;
            g_idx[k] = fi;
            sm[fi]   = -3.0e38f;
        }
        __syncthreads();
    }

    if (t < B_) {
        const int b = t;
        float w[K_];
        float m = -3.0e38f;
#pragma unroll
        for (int k = 0; k < K_; ++k) {
            w[k] = g_meanv[(size_t)b * L_ + s_idx[k]];
            m = fmaxf(m, w[k]);
        }
        float sum = 0.f;
#pragma unroll
        for (int k = 0; k < K_; ++k) { w[k] = __expf(w[k] - m); sum += w[k]; }
        const float inv = 1.0f / sum;
#pragma unroll
        for (int k = 0; k < K_; ++k) g_wts[b * K_ + k] = w[k] * inv;
    }
}

// ---------------------------------------------------------------------------
// Kernel 4: delays aggregation, row-pair interleaved + packed FFMA2.
// Rows staged in interleaved pairs: sv[2x]=rowA[x], sv[2x+1]=rowB[x], so one
// aligned LDS.64 at 8*((l+i_k)&1023) feeds TWO outputs, and one fma.rn.f32x2
// does both multiplies -> ~half the issue slots of the scalar version at the
// same crossbar bytes. Stores use __stcs (streaming) so the 64MB of output
// doesn't evict the prefetched values from L2.
// ---------------------------------------------------------------------------
__global__ __launch_bounds__(256) void k_agg(const float* __restrict__ values,
                                             float* __restrict__ out) {
    __shared__ float sv[TROWS * L_];        // 16 KB: 2 interleaved pairs
    const int t    = threadIdx.x;
    const int row0 = blockIdx.x * TROWS;    // 4 rows, same batch b
    const int b    = row0 >> 9;             // row0 / (H_*C_)

    // stage 2 pairs interleaved (4 independent LDG.128 per thread)
    const float4* __restrict__ src =
        reinterpret_cast<const float4*>(values + (size_t)row0 * L_);
    float4* sv4 = reinterpret_cast<float4*>(sv);
#pragma unroll
    for (int p = 0; p < TROWS / 2; ++p) {
        float4 a = src[(2 * p)     * 256 + t];   // row A of pair p
        float4 c = src[(2 * p + 1) * 256 + t];   // row B of pair p
        sv4[p * 512 + 2 * t]     = make_float4(a.x, c.x, a.y, c.y);
        sv4[p * 512 + 2 * t + 1] = make_float4(a.z, c.z, a.w, c.w);
    }

    // broadcast weights (packed duplicated) + indices
    uint64_t w2[K_];
    int      ix[K_];
#pragma unroll
    for (int k = 0; k < K_; ++k) {
        const float w = g_wts[b * K_ + k];
        w2[k] = pack2(w, w);
        ix[k] = g_idx[k];
    }

    __syncthreads();

#pragma unroll
    for (int p = 0; p < TROWS / 2; ++p) {
        const float2* sp2 = reinterpret_cast<const float2*>(sv + p * 2 * L_);
        float* dA = out + (size_t)(row0 + 2 * p) * L_;
        float* dB = dA + L_;
#pragma unroll
        for (int j = 0; j < 4; ++j) {
            const int l = t + j * 256;
            uint64_t acc = 0;                     // (0.0f, 0.0f)
#pragma unroll
            for (int k = 0; k < K_; ++k) {
                const float2 v = sp2[(l + ix[k]) & (L_ - 1)];   // LDS.64
                acc = fma2(pack2(v.x, v.y), w2[k], acc);        // FFMA2
            }
            float ra, rb;
            unpack2(acc, ra, rb);
            __stcs(&dA[l], ra);
            __stcs(&dB[l], rb);
        }
    }
}

// ---------------------------------------------------------------------------
extern "C" void kernel_launch(void* const* d_in, const int* in_sizes, int n_in,
                              void* d_out, int out_size) {
    const float* values = (const float*)d_in[0];
    const float* corr   = (const float*)d_in[1];
    float*       out    = (float*)d_out;

    dim3 g1(B_, G_);
    k_partial<<<g1, 256>>>(corr, values);
    dim3 g2(B_, 4);
    k_combine<<<g2, 256>>>();
    k_topk_softmax<<<1, 256>>>();
    k_agg<<<(B_ * H_ * C_) / TROWS, 256>>>(values, out);
}